// round 1
// baseline (speedup 1.0000x reference)
#include <cuda_runtime.h>
#include <math.h>

#define TN 16000
#define NT 512
#define NF 36
#define NB 64
#define NOUT 250
#define DH 256
#define NTAPS 513
#define KPHI 569
#define NCH 37

// ---------------- static device scratch (no runtime allocation) ----------------
__device__ float2 d_X[NB * TN];        // scrambled forward FFT of x (8 MB)
__device__ float  d_psiw[NF * TN];     // psi_hat (scrambled order) / TN (2.3 MB)
__device__ float  d_phiw[NTAPS];       // time-domain lowpass taps
__device__ float  d_S1[NB * NCH * NOUT];

// ---------------- complex helpers ----------------
__device__ __forceinline__ float2 cmul(float2 a, float2 b) {
    return make_float2(a.x*b.x - a.y*b.y, a.x*b.y + a.y*b.x);
}
__device__ __forceinline__ float2 cadd(float2 a, float2 b){ return make_float2(a.x+b.x, a.y+b.y); }
__device__ __forceinline__ float2 csub(float2 a, float2 b){ return make_float2(a.x-b.x, a.y-b.y); }
__device__ __forceinline__ int pad(int n){ return n + (n >> 5); }   // bank-conflict padding

// ---------------- prep kernels (cheap, rerun each launch for determinism) ----------------
__global__ void prep_phi() {
    int tap  = blockIdx.x;          // 0..NTAPS-1
    int lane = threadIdx.x;         // 32 threads per tap
    int d = tap - DH;
    const double sp = 0.35 / 64.0;
    const double PI2 = 6.283185307179586476925286766559;
    double acc = 0.0;
    for (int k = 1 + lane; k <= KPHI; k += 32) {
        double f = (double)k / (double)TN;
        double g = exp(-f*f / (2.0*sp*sp));
        acc += g * cos(PI2 * (double)k * (double)d / (double)TN);
    }
    for (int o = 16; o; o >>= 1) acc += __shfl_down_sync(0xffffffffu, acc, o);
    if (lane == 0) d_phiw[tap] = (float)((1.0 + 2.0*acc) / (double)TN);
}

__global__ void prep_psi() {
    int p = blockIdx.x * blockDim.x + threadIdx.x;
    if (p >= TN) return;
    // digit-reversal: DIF radices [5,5,5,4,4,4,2]; position p -> frequency k
    int k = (p/3200) + 5*((p/640)%5) + 25*((p/128)%5)
          + 125*((p/32)%4) + 500*((p/8)%4) + 2000*((p/2)%4) + 8000*(p&1);
    double f = (k < TN/2) ? (double)k / (double)TN : (double)(k - TN) / (double)TN;
    const double r   = pow(2.0, 1.0/6.0);
    const double fac = (r - 1.0) / (r + 1.0);
    #pragma unroll 1
    for (int j = 0; j < NF; ++j) {
        double xi = 0.35 * pow(2.0, -(double)j/6.0);
        double sg = xi * fac;
        double u  = (f - xi) / sg;
        double v  = (u*u < 400.0) ? exp(-0.5*u*u) : 0.0;   // < 1e-87 -> 0 in f32 anyway
        d_psiw[j*TN + p] = (float)(v / (double)TN);        // fold ifft 1/N into the filter
    }
}

// ---------------- small-radix DFTs (SIGN = -1 forward, +1 inverse) ----------------
template<int SIGN>
__device__ __forceinline__ void dft4(float2&z0,float2&z1,float2&z2,float2&z3){
    float2 t0=cadd(z0,z2), t1=csub(z0,z2), t2=cadd(z1,z3), t3=csub(z1,z3);
    const float s = (float)SIGN;
    z0 = cadd(t0,t2);
    z2 = csub(t0,t2);
    z1 = make_float2(t1.x - s*t3.y, t1.y + s*t3.x);
    z3 = make_float2(t1.x + s*t3.y, t1.y - s*t3.x);
}

template<int SIGN>
__device__ __forceinline__ void dft5(float2&z0,float2&z1,float2&z2,float2&z3,float2&z4){
    const float K1 =  0.309016994374947424f;   // cos(2pi/5)
    const float K2 = -0.809016994374947424f;   // cos(4pi/5)
    const float S1 =  0.951056516295153572f;   // sin(2pi/5)
    const float S2 =  0.587785252292473129f;   // sin(4pi/5)
    float2 t1=cadd(z1,z4), t2=cadd(z2,z3), t3=csub(z1,z4), t4=csub(z2,z3);
    float2 a = z0;
    float2 sum = cadd(a, cadd(t1,t2));
    float2 r1 = make_float2(a.x + K1*t1.x + K2*t2.x, a.y + K1*t1.y + K2*t2.y);
    float2 r2 = make_float2(a.x + K2*t1.x + K1*t2.x, a.y + K2*t1.y + K1*t2.y);
    float2 q1 = make_float2(S1*t3.x + S2*t4.x, S1*t3.y + S2*t4.y);
    float2 q2 = make_float2(S2*t3.x - S1*t4.x, S2*t3.y - S1*t4.y);
    const float s = (float)SIGN;
    z0 = sum;
    z1 = make_float2(r1.x - s*q1.y, r1.y + s*q1.x);
    z4 = make_float2(r1.x + s*q1.y, r1.y - s*q1.x);
    z2 = make_float2(r2.x - s*q2.y, r2.y + s*q2.x);
    z3 = make_float2(r2.x + s*q2.y, r2.y - s*q2.x);
}

// twiddle W_16000^{-x} from two small tables: x = 125*a + b
__device__ __forceinline__ float2 twb(int x, const float2* rtA, const float2* rtB){
    int a = x / 125;
    return cmul(rtA[a], rtB[x - a*125]);
}

// ---------------- FFT stages (in-place, blocked) ----------------
// Forward (SIGN<0): u_s = DFT_R(z); store u_s * W_n^{-p s} at base+p+M*s.
// Inverse (SIGN>0): v_s = y_s * W_n^{+p s}; z = DFT_R^{+}(v); store at same slots.
template<int M, int C, int SIGN>
__device__ void stage5(float2* buf, const float2* rtA, const float2* rtB){
    for (int idx = threadIdx.x; idx < TN/5; idx += NT) {
        int blk = idx / M;
        int p   = idx - blk*M;
        int o   = blk*(5*M) + p;
        float2 z0=buf[o], z1=buf[o+M], z2=buf[o+2*M], z3=buf[o+3*M], z4=buf[o+4*M];
        int x = C*p;
        float2 w1=twb(x,rtA,rtB), w2=twb(2*x,rtA,rtB), w3=twb(3*x,rtA,rtB), w4=twb(4*x,rtA,rtB);
        if (SIGN > 0) {
            w1.y=-w1.y; w2.y=-w2.y; w3.y=-w3.y; w4.y=-w4.y;
            z1=cmul(z1,w1); z2=cmul(z2,w2); z3=cmul(z3,w3); z4=cmul(z4,w4);
        }
        dft5<SIGN>(z0,z1,z2,z3,z4);
        if (SIGN < 0) { z1=cmul(z1,w1); z2=cmul(z2,w2); z3=cmul(z3,w3); z4=cmul(z4,w4); }
        buf[o]=z0; buf[o+M]=z1; buf[o+2*M]=z2; buf[o+3*M]=z3; buf[o+4*M]=z4;
    }
    __syncthreads();
}

template<int M, int C, int SIGN>   // C = 128 / n_cur
__device__ void stage4(float2* buf, const float2* rtA){
    for (int idx = threadIdx.x; idx < TN/4; idx += NT) {
        int blk = idx / M;
        int p   = idx - blk*M;
        int o   = blk*(4*M) + p;
        float2 z0=buf[o], z1=buf[o+M], z2=buf[o+2*M], z3=buf[o+3*M];
        int x = C*p;
        float2 w1=rtA[x], w2=rtA[2*x], w3=rtA[3*x];
        if (SIGN > 0) {
            w1.y=-w1.y; w2.y=-w2.y; w3.y=-w3.y;
            z1=cmul(z1,w1); z2=cmul(z2,w2); z3=cmul(z3,w3);
        }
        dft4<SIGN>(z0,z1,z2,z3);
        if (SIGN < 0) { z1=cmul(z1,w1); z2=cmul(z2,w2); z3=cmul(z3,w3); }
        buf[o]=z0; buf[o+M]=z1; buf[o+2*M]=z2; buf[o+3*M]=z3;
    }
    __syncthreads();
}

__device__ void stage2(float2* buf){   // n_cur=2: no twiddle, self-inverse (scale folded)
    for (int idx = threadIdx.x; idx < TN/2; idx += NT) {
        int o = 2*idx;
        float2 a=buf[o], b=buf[o+1];
        buf[o]=cadd(a,b); buf[o+1]=csub(a,b);
    }
    __syncthreads();
}

__device__ void init_tables(float2* rtA, float2* rtB, float* sphi){
    for (int i = threadIdx.x; i < 128; i += NT) {
        double sv, cv; sincospi(-(double)i/64.0,   &sv, &cv);
        rtA[i] = make_float2((float)cv, (float)sv);
    }
    for (int i = threadIdx.x; i < 125; i += NT) {
        double sv, cv; sincospi(-(double)i/8000.0, &sv, &cv);
        rtB[i] = make_float2((float)cv, (float)sv);
    }
    for (int i = threadIdx.x; i < NTAPS; i += NT) sphi[i] = d_phiw[i];
}

// 513-tap circular conv, sampled every 64 -> 250 outputs
__device__ void smooth(const float* Upad, const float* sphi, float* dst){
    for (int m0 = threadIdx.x; m0 < NOUT; m0 += NT) {
        float acc = 0.f;
        int idx = 64*m0 + DH; if (idx >= TN) idx -= TN;
        #pragma unroll 4
        for (int t = 0; t < NTAPS; ++t) {
            acc += sphi[t] * Upad[pad(idx)];
            if (--idx < 0) idx += TN;
        }
        dst[m0] = acc;
    }
}

// ---------------- kernel 1: forward FFT of x (+ S0) ----------------
__global__ __launch_bounds__(NT, 1) void k_fwd(const float* __restrict__ x){
    extern __shared__ __align__(16) unsigned char sm[];
    float2* buf = (float2*)sm;                       // 16000 complex
    float*  xs  = (float*)(sm + TN*sizeof(float2));  // padded 16500 floats
    __shared__ float2 rtA[128]; __shared__ float2 rtB[125]; __shared__ float sphi[NTAPS];
    int b = blockIdx.x;
    init_tables(rtA, rtB, sphi);
    const float* xb = x + b*TN;
    for (int n = threadIdx.x; n < TN; n += NT) xs[pad(n)] = xb[n];
    __syncthreads();
    smooth(xs, sphi, &d_S1[(b*NCH + 0)*NOUT]);       // S0 directly in time domain
    for (int n = threadIdx.x; n < TN; n += NT) buf[n] = make_float2(xs[pad(n)], 0.f);
    __syncthreads();
    stage5<3200,1,-1>(buf, rtA, rtB);
    stage5<640,5,-1>(buf, rtA, rtB);
    stage5<128,25,-1>(buf, rtA, rtB);
    stage4<32,1,-1>(buf, rtA);
    stage4<8,4,-1>(buf, rtA);
    stage4<2,16,-1>(buf, rtA);
    stage2(buf);
    float2* Xo = d_X + b*TN;
    for (int p = threadIdx.x; p < TN; p += NT) Xo[p] = buf[p];   // stored scrambled
}

// ---------------- kernel 2: per (filter, batch) band-pass ifft + |.| + smoothing ----------------
__global__ __launch_bounds__(NT, 1) void k_band(){
    extern __shared__ __align__(16) unsigned char sm[];
    float2* buf = (float2*)sm;
    float*  U   = (float*)(sm + TN*sizeof(float2));
    __shared__ float2 rtA[128]; __shared__ float2 rtB[125]; __shared__ float sphi[NTAPS];
    int j = blockIdx.x, b = blockIdx.y;
    init_tables(rtA, rtB, sphi);
    const float2* Xb = d_X + b*TN;
    const float*  pw = d_psiw + j*TN;
    for (int p = threadIdx.x; p < TN; p += NT) {
        float2 v = Xb[p]; float w = pw[p];
        buf[p] = make_float2(v.x*w, v.y*w);
    }
    __syncthreads();
    // inverse: exact mirror of forward stage list, conjugate twiddles
    stage2(buf);
    stage4<2,16,1>(buf, rtA);
    stage4<8,4,1>(buf, rtA);
    stage4<32,1,1>(buf, rtA);
    stage5<128,25,1>(buf, rtA, rtB);
    stage5<640,5,1>(buf, rtA, rtB);
    stage5<3200,1,1>(buf, rtA, rtB);
    for (int n = threadIdx.x; n < TN; n += NT) {
        float2 z = buf[n];
        U[pad(n)] = sqrtf(z.x*z.x + z.y*z.y);
    }
    __syncthreads();
    smooth(U, sphi, &d_S1[(b*NCH + 1 + j)*NOUT]);
}

// ---------------- kernel 3: channel-group means ----------------
__global__ void k_reduce(float* __restrict__ out){
    int i = blockIdx.x * blockDim.x + threadIdx.x;
    if (i >= NB*3*NOUT) return;
    int m0 = i % NOUT;
    int g  = (i / NOUT) % 3;
    int b  = i / (3*NOUT);
    int c0 = (g==0) ? 0 : (g==1 ? 12 : 24);
    int nc = (g==2) ? 13 : 12;
    float acc = 0.f;
    for (int c = 0; c < nc; ++c) acc += d_S1[(b*NCH + c0 + c)*NOUT + m0];
    out[i] = acc / (float)nc;
}

// ---------------- launch ----------------
extern "C" void kernel_launch(void* const* d_in, const int* in_sizes, int n_in,
                              void* d_out, int out_size) {
    (void)in_sizes; (void)n_in; (void)out_size;
    const float* x = (const float*)d_in[0];
    float* out = (float*)d_out;
    const int smbytes = TN*(int)sizeof(float2) + (TN + TN/32)*(int)sizeof(float); // 194000
    cudaFuncSetAttribute(k_fwd,  cudaFuncAttributeMaxDynamicSharedMemorySize, smbytes);
    cudaFuncSetAttribute(k_band, cudaFuncAttributeMaxDynamicSharedMemorySize, smbytes);
    prep_phi<<<NTAPS, 32>>>();
    prep_psi<<<(TN + 255)/256, 256>>>();
    k_fwd<<<NB, NT, smbytes>>>(x);
    k_band<<<dim3(NF, NB), NT, smbytes>>>();
    k_reduce<<<(NB*3*NOUT + 255)/256, 256>>>(out);
}

// round 3
// speedup vs baseline: 1.3105x; 1.3105x over previous
#include <cuda_runtime.h>
#include <math.h>

#define TN 16000
#define NT 1024
#define NF 36
#define NB 64
#define NOUT 250
#define DH 256
#define NTAPS 513
#define KPHI 569
#define NCH 37

// ---------------- static device scratch ----------------
__device__ float2 d_X[NB * TN];        // scrambled forward FFT of x (8 MB)
__device__ float  d_psiw[NF * TN];     // psi_hat (scrambled order) / TN
__device__ float  d_phiw[NTAPS];       // time-domain lowpass taps
__device__ float  d_S1[NB * NCH * NOUT];

// ---------------- complex helpers ----------------
__device__ __forceinline__ float2 cmul(float2 a, float2 b) {
    return make_float2(a.x*b.x - a.y*b.y, a.x*b.y + a.y*b.x);
}
__device__ __forceinline__ float2 cadd(float2 a, float2 b){ return make_float2(a.x+b.x, a.y+b.y); }
__device__ __forceinline__ float2 csub(float2 a, float2 b){ return make_float2(a.x-b.x, a.y-b.y); }
__device__ __forceinline__ int pad(int n){ return n + (n >> 5); }

// ---------------- prep kernels ----------------
__global__ void prep_phi() {
    int tap  = blockIdx.x;
    int lane = threadIdx.x;
    int d = tap - DH;
    const double sp = 0.35 / 64.0;
    const double PI2 = 6.283185307179586476925286766559;
    double acc = 0.0;
    for (int k = 1 + lane; k <= KPHI; k += 32) {
        double f = (double)k / (double)TN;
        double g = exp(-f*f / (2.0*sp*sp));
        acc += g * cos(PI2 * (double)k * (double)d / (double)TN);
    }
    for (int o = 16; o; o >>= 1) acc += __shfl_down_sync(0xffffffffu, acc, o);
    if (lane == 0) d_phiw[tap] = (float)((1.0 + 2.0*acc) / (double)TN);
}

__global__ void prep_psi() {
    int p = blockIdx.x * blockDim.x + threadIdx.x;
    if (p >= TN) return;
    // digit reversal for DIF radices [2,4,4,4,5,5,5] (position p -> frequency k)
    int k = (p/8000) + 2*((p/2000)%4) + 8*((p/500)%4) + 32*((p/125)%4)
          + 128*((p/25)%5) + 640*((p/5)%5) + 3200*(p%5);
    double f = (k < TN/2) ? (double)k / (double)TN : (double)(k - TN) / (double)TN;
    const double r   = pow(2.0, 1.0/6.0);
    const double fac = (r - 1.0) / (r + 1.0);
    #pragma unroll 1
    for (int j = 0; j < NF; ++j) {
        double xi = 0.35 * pow(2.0, -(double)j/6.0);
        double sg = xi * fac;
        double u  = (f - xi) / sg;
        double v  = (u*u < 400.0) ? exp(-0.5*u*u) : 0.0;
        d_psiw[j*TN + p] = (float)(v / (double)TN);
    }
}

// ---------------- small DFTs (SIGN = -1 forward, +1 inverse) ----------------
template<int SIGN>
__device__ __forceinline__ void dft4(float2&z0,float2&z1,float2&z2,float2&z3){
    float2 t0=cadd(z0,z2), t1=csub(z0,z2), t2=cadd(z1,z3), t3=csub(z1,z3);
    const float s = (float)SIGN;
    z0 = cadd(t0,t2);
    z2 = csub(t0,t2);
    z1 = make_float2(t1.x - s*t3.y, t1.y + s*t3.x);
    z3 = make_float2(t1.x + s*t3.y, t1.y - s*t3.x);
}

template<int SIGN>
__device__ __forceinline__ void dft5(float2&z0,float2&z1,float2&z2,float2&z3,float2&z4){
    const float K1 =  0.309016994374947424f;
    const float K2 = -0.809016994374947424f;
    const float S1 =  0.951056516295153572f;
    const float S2 =  0.587785252292473129f;
    float2 t1=cadd(z1,z4), t2=cadd(z2,z3), t3=csub(z1,z4), t4=csub(z2,z3);
    float2 a = z0;
    float2 sum = cadd(a, cadd(t1,t2));
    float2 r1 = make_float2(a.x + K1*t1.x + K2*t2.x, a.y + K1*t1.y + K2*t2.y);
    float2 r2 = make_float2(a.x + K2*t1.x + K1*t2.x, a.y + K2*t1.y + K1*t2.y);
    float2 q1 = make_float2(S1*t3.x + S2*t4.x, S1*t3.y + S2*t4.y);
    float2 q2 = make_float2(S2*t3.x - S1*t4.x, S2*t3.y - S1*t4.y);
    const float s = (float)SIGN;
    z0 = sum;
    z1 = make_float2(r1.x - s*q1.y, r1.y + s*q1.x);
    z4 = make_float2(r1.x + s*q1.y, r1.y - s*q1.x);
    z2 = make_float2(r2.x - s*q2.y, r2.y + s*q2.x);
    z3 = make_float2(r2.x + s*q2.y, r2.y - s*q2.x);
}

// twiddle W_16000^{-x}, x in [0,16000): x = 125a + b
__device__ __forceinline__ float2 twb(int x, const float2* rtA, const float2* rtB){
    int a = x / 125;
    return cmul(rtA[a], rtB[x - a*125]);
}

// ---------------- fused radix-8 (= radix-2 M=8000 then radix-4 M=2000) ----------------
template<int SIGN>
__device__ void stage8f(float2* buf, const float2* rtA, const float2* rtB){
    const float H = 0.70710678118654752f;
    for (int p = threadIdx.x; p < 2000; p += NT) {
        float2 z[8];
        #pragma unroll
        for (int i=0;i<8;i++) z[i] = buf[p + 2000*i];
        float2 wp = twb(p,   rtA, rtB); if (SIGN>0) wp.y = -wp.y;
        float2 w2 = twb(2*p, rtA, rtB); if (SIGN>0) w2.y = -w2.y;
        float2 w4 = cmul(w2,w2), w6 = cmul(w4,w2);
        if (SIGN < 0) {
            #pragma unroll
            for (int i=0;i<4;i++){
                float2 a=z[i], b=z[i+4];
                z[i]=cadd(a,b);
                float2 t = cmul(csub(a,b), wp);
                if (i==1) t = cmul(t, make_float2( H,-H));
                else if (i==2) t = make_float2(t.y, -t.x);
                else if (i==3) t = cmul(t, make_float2(-H,-H));
                z[i+4]=t;
            }
            dft4<-1>(z[0],z[1],z[2],z[3]);
            dft4<-1>(z[4],z[5],z[6],z[7]);
            z[1]=cmul(z[1],w2); z[2]=cmul(z[2],w4); z[3]=cmul(z[3],w6);
            z[5]=cmul(z[5],w2); z[6]=cmul(z[6],w4); z[7]=cmul(z[7],w6);
        } else {
            z[1]=cmul(z[1],w2); z[2]=cmul(z[2],w4); z[3]=cmul(z[3],w6);
            z[5]=cmul(z[5],w2); z[6]=cmul(z[6],w4); z[7]=cmul(z[7],w6);
            dft4<1>(z[0],z[1],z[2],z[3]);
            dft4<1>(z[4],z[5],z[6],z[7]);
            #pragma unroll
            for (int i=0;i<4;i++){
                float2 t = cmul(z[i+4], wp);
                if (i==1) t = cmul(t, make_float2( H, H));
                else if (i==2) t = make_float2(-t.y, t.x);
                else if (i==3) t = cmul(t, make_float2(-H, H));
                float2 a=z[i];
                z[i]=cadd(a,t); z[i+4]=csub(a,t);
            }
        }
        #pragma unroll
        for (int i=0;i<8;i++) buf[p + 2000*i] = z[i];
    }
    __syncthreads();
}

// ---------------- fused radix-16 (= radix-4 M=500 then radix-4 M=125), blocks of 2000 ----------------
template<int SIGN>
__device__ void stage16f(float2* buf, const float2* rtA, const float2* rtB){
    const float CA = 0.92387953251128674f, SA = 0.38268343236508977f;
    const float H  = 0.70710678118654752f;
    for (int idx = threadIdx.x; idx < 1000; idx += NT) {
        int blk = idx / 125;
        int p   = idx - blk*125;
        int o   = blk*2000 + p;
        float2 z[16];
        #pragma unroll
        for (int i=0;i<16;i++) z[i] = buf[o + 125*i];
        float2 w1 = twb(8*p,  rtA, rtB); if (SIGN>0) w1.y=-w1.y;
        float2 w2 = twb(32*p, rtA, rtB); if (SIGN>0) w2.y=-w2.y;
        float2 w2b = cmul(w2,w2), w2c = cmul(w2b,w2);
        const float sgn = (SIGN<0)? 1.f : -1.f;
        float2 c16[4];
        c16[0] = make_float2(1.f, 0.f);
        c16[1] = make_float2(CA, -sgn*SA);
        c16[2] = make_float2( H, -sgn*H);
        c16[3] = make_float2(SA, -sgn*CA);
        if (SIGN < 0) {
            #pragma unroll
            for (int u=0;u<4;u++){
                dft4<-1>(z[u], z[u+4], z[u+8], z[u+12]);
                float2 t  = cmul(w1, c16[u]);
                float2 t2 = cmul(t,t);
                z[u+4]  = cmul(z[u+4],  t);
                z[u+8]  = cmul(z[u+8],  t2);
                z[u+12] = cmul(z[u+12], cmul(t2,t));
            }
            #pragma unroll
            for (int s=0;s<4;s++){
                dft4<-1>(z[4*s], z[4*s+1], z[4*s+2], z[4*s+3]);
                z[4*s+1]=cmul(z[4*s+1],w2); z[4*s+2]=cmul(z[4*s+2],w2b); z[4*s+3]=cmul(z[4*s+3],w2c);
            }
        } else {
            #pragma unroll
            for (int s=0;s<4;s++){
                z[4*s+1]=cmul(z[4*s+1],w2); z[4*s+2]=cmul(z[4*s+2],w2b); z[4*s+3]=cmul(z[4*s+3],w2c);
                dft4<1>(z[4*s], z[4*s+1], z[4*s+2], z[4*s+3]);
            }
            #pragma unroll
            for (int u=0;u<4;u++){
                float2 t  = cmul(w1, c16[u]);
                float2 t2 = cmul(t,t);
                z[u+4]  = cmul(z[u+4],  t);
                z[u+8]  = cmul(z[u+8],  t2);
                z[u+12] = cmul(z[u+12], cmul(t2,t));
                dft4<1>(z[u], z[u+4], z[u+8], z[u+12]);
            }
        }
        #pragma unroll
        for (int i=0;i<16;i++) buf[o + 125*i] = z[i];
    }
    __syncthreads();
}

// ---------------- radix-5 stage (sub-transform length 5M, twiddle W^{-C p s}) ----------------
template<int M, int C, int SIGN>
__device__ void stage5n(float2* buf, const float2* rtA, const float2* rtB){
    for (int idx = threadIdx.x; idx < 3200; idx += NT) {
        int blk = idx / M;
        int p   = idx - blk*M;
        int o   = blk*(5*M) + p;
        float2 z0=buf[o], z1=buf[o+M], z2=buf[o+2*M], z3=buf[o+3*M], z4=buf[o+4*M];
        if (M > 1) {
            float2 w = twb(C*p, rtA, rtB); if (SIGN>0) w.y=-w.y;
            float2 ww = cmul(w,w);
            float2 w3 = cmul(ww,w);
            float2 w4 = cmul(ww,ww);
            if (SIGN > 0) {
                z1=cmul(z1,w); z2=cmul(z2,ww); z3=cmul(z3,w3); z4=cmul(z4,w4);
                dft5<1>(z0,z1,z2,z3,z4);
            } else {
                dft5<-1>(z0,z1,z2,z3,z4);
                z1=cmul(z1,w); z2=cmul(z2,ww); z3=cmul(z3,w3); z4=cmul(z4,w4);
            }
        } else {
            dft5<SIGN>(z0,z1,z2,z3,z4);
        }
        buf[o]=z0; buf[o+M]=z1; buf[o+2*M]=z2; buf[o+3*M]=z3; buf[o+4*M]=z4;
    }
    __syncthreads();
}

__device__ void init_tables(float2* rtA, float2* rtB, float* sphi){
    for (int i = threadIdx.x; i < 128; i += NT) {
        double sv, cv; sincospi(-(double)i/64.0,   &sv, &cv);
        rtA[i] = make_float2((float)cv, (float)sv);
    }
    for (int i = threadIdx.x; i < 125; i += NT) {
        double sv, cv; sincospi(-(double)i/8000.0, &sv, &cv);
        rtB[i] = make_float2((float)cv, (float)sv);
    }
    for (int i = threadIdx.x; i < NTAPS; i += NT) sphi[i] = d_phiw[i];
}

// 513-tap circular conv sampled every 64; 4 threads per output
__device__ void smooth(const float* Upad, const float* sphi, float* dst){
    int tid = threadIdx.x;
    int m0 = tid >> 2;
    int r  = tid & 3;
    float acc = 0.f;
    if (m0 < NOUT) {
        int idx = 64*m0 + DH - r; if (idx >= TN) idx -= TN;
        for (int t = r; t < NTAPS; t += 4) {
            acc += sphi[t] * Upad[pad(idx)];
            idx -= 4; if (idx < 0) idx += TN;
        }
    }
    acc += __shfl_down_sync(0xffffffffu, acc, 1);
    acc += __shfl_down_sync(0xffffffffu, acc, 2);
    if (r == 0 && m0 < NOUT) dst[m0] = acc;
}

// ---------------- kernel 1: forward FFT of x (+ S0) ----------------
__global__ __launch_bounds__(NT, 1) void k_fwd(const float* __restrict__ x){
    extern __shared__ __align__(16) unsigned char sm[];
    float2* buf = (float2*)sm;
    float*  xs  = (float*)(sm + TN*sizeof(float2));
    __shared__ float2 rtA[128]; __shared__ float2 rtB[125]; __shared__ float sphi[NTAPS];
    int b = blockIdx.x;
    init_tables(rtA, rtB, sphi);
    const float* xb = x + b*TN;
    for (int n = threadIdx.x; n < TN; n += NT) xs[pad(n)] = xb[n];
    __syncthreads();
    smooth(xs, sphi, &d_S1[(b*NCH + 0)*NOUT]);
    for (int n = threadIdx.x; n < TN; n += NT) buf[n] = make_float2(xs[pad(n)], 0.f);
    __syncthreads();
    stage8f<-1>(buf, rtA, rtB);
    stage16f<-1>(buf, rtA, rtB);
    stage5n<25,128,-1>(buf, rtA, rtB);
    stage5n<5,640,-1>(buf, rtA, rtB);
    stage5n<1,0,-1>(buf, rtA, rtB);
    float2* Xo = d_X + b*TN;
    for (int p = threadIdx.x; p < TN; p += NT) Xo[p] = buf[p];
}

// ---------------- kernel 2: band-pass ifft + |.| + smoothing ----------------
__global__ __launch_bounds__(NT, 1) void k_band(){
    extern __shared__ __align__(16) unsigned char sm[];
    float2* buf = (float2*)sm;
    float*  U   = (float*)(sm + TN*sizeof(float2));
    __shared__ float2 rtA[128]; __shared__ float2 rtB[125]; __shared__ float sphi[NTAPS];
    int j = blockIdx.x, b = blockIdx.y;
    init_tables(rtA, rtB, sphi);
    const float2* Xb = d_X + b*TN;
    const float*  pw = d_psiw + j*TN;
    for (int p = threadIdx.x; p < TN; p += NT) {
        float2 v = Xb[p]; float w = pw[p];
        buf[p] = make_float2(v.x*w, v.y*w);
    }
    __syncthreads();
    stage5n<1,0,1>(buf, rtA, rtB);
    stage5n<5,640,1>(buf, rtA, rtB);
    stage5n<25,128,1>(buf, rtA, rtB);
    stage16f<1>(buf, rtA, rtB);
    stage8f<1>(buf, rtA, rtB);
    for (int n = threadIdx.x; n < TN; n += NT) {
        float2 z = buf[n];
        U[pad(n)] = sqrtf(z.x*z.x + z.y*z.y);
    }
    __syncthreads();
    smooth(U, sphi, &d_S1[(b*NCH + 1 + j)*NOUT]);
}

// ---------------- kernel 3: channel-group means ----------------
__global__ void k_reduce(float* __restrict__ out){
    int i = blockIdx.x * blockDim.x + threadIdx.x;
    if (i >= NB*3*NOUT) return;
    int m0 = i % NOUT;
    int g  = (i / NOUT) % 3;
    int b  = i / (3*NOUT);
    int c0 = (g==0) ? 0 : (g==1 ? 12 : 24);
    int nc = (g==2) ? 13 : 12;
    float acc = 0.f;
    for (int c = 0; c < nc; ++c) acc += d_S1[(b*NCH + c0 + c)*NOUT + m0];
    out[i] = acc / (float)nc;
}

// ---------------- launch ----------------
extern "C" void kernel_launch(void* const* d_in, const int* in_sizes, int n_in,
                              void* d_out, int out_size) {
    (void)in_sizes; (void)n_in; (void)out_size;
    const float* x = (const float*)d_in[0];
    float* out = (float*)d_out;
    const int smbytes = TN*(int)sizeof(float2) + (TN + TN/32 + 4)*(int)sizeof(float);
    cudaFuncSetAttribute(k_fwd,  cudaFuncAttributeMaxDynamicSharedMemorySize, smbytes);
    cudaFuncSetAttribute(k_band, cudaFuncAttributeMaxDynamicSharedMemorySize, smbytes);
    prep_phi<<<NTAPS, 32>>>();
    prep_psi<<<(TN + 255)/256, 256>>>();
    k_fwd<<<NB, NT, smbytes>>>(x);
    k_band<<<dim3(NF, NB), NT, smbytes>>>();
    k_reduce<<<(NB*3*NOUT + 255)/256, 256>>>(out);
}

// round 4
// speedup vs baseline: 1.5488x; 1.1818x over previous
#include <cuda_runtime.h>
#include <math.h>

#define TN 16000
#define NT 1024
#define NF 36
#define NB 64
#define NOUT 250
#define DH 160
#define NTAPS 321
#define KPHI 569
#define NCH 37

// ---------------- static device scratch ----------------
__device__ float2 d_X[NB * TN];        // scrambled forward FFT of x (8 MB, L2-resident)
__device__ float  d_psiw[NF * TN];     // psi_hat (scrambled order) / TN
__device__ float  d_phiw[NTAPS];       // time-domain lowpass taps
__device__ float2 d_rtA[128];          // W_16000^{-125 i}
__device__ float2 d_rtB[125];          // W_16000^{-i}
__device__ float  d_S1[NB * NCH * NOUT];

// ---------------- complex helpers ----------------
__device__ __forceinline__ float2 cmul(float2 a, float2 b) {
    return make_float2(a.x*b.x - a.y*b.y, a.x*b.y + a.y*b.x);
}
__device__ __forceinline__ float2 cadd(float2 a, float2 b){ return make_float2(a.x+b.x, a.y+b.y); }
__device__ __forceinline__ float2 csub(float2 a, float2 b){ return make_float2(a.x-b.x, a.y-b.y); }

// ---------------- prep kernels ----------------
__global__ void prep_phi() {
    int tap  = blockIdx.x;
    int lane = threadIdx.x;
    int d = tap - DH;
    const double sp = 0.35 / 64.0;
    const double PI2 = 6.283185307179586476925286766559;
    double acc = 0.0;
    for (int k = 1 + lane; k <= KPHI; k += 32) {
        double f = (double)k / (double)TN;
        double g = exp(-f*f / (2.0*sp*sp));
        acc += g * cos(PI2 * (double)k * (double)d / (double)TN);
    }
    for (int o = 16; o; o >>= 1) acc += __shfl_down_sync(0xffffffffu, acc, o);
    if (lane == 0) d_phiw[tap] = (float)((1.0 + 2.0*acc) / (double)TN);
}

__global__ void prep_tw() {
    int i = threadIdx.x;
    if (i < 128) { double s, c; sincospi(-(double)i/64.0,   &s, &c); d_rtA[i] = make_float2((float)c, (float)s); }
    if (i < 125) { double s, c; sincospi(-(double)i/8000.0, &s, &c); d_rtB[i] = make_float2((float)c, (float)s); }
}

__global__ void prep_psi() {
    int p = blockIdx.x * blockDim.x + threadIdx.x;
    if (p >= TN) return;
    // digit reversal for DIF radices [2,4,4,4,5,5,5] (position p -> frequency k)
    int k = (p/8000) + 2*((p/2000)%4) + 8*((p/500)%4) + 32*((p/125)%4)
          + 128*((p/25)%5) + 640*((p/5)%5) + 3200*(p%5);
    double f = (k < TN/2) ? (double)k / (double)TN : (double)(k - TN) / (double)TN;
    const double r   = pow(2.0, 1.0/6.0);
    const double fac = (r - 1.0) / (r + 1.0);
    #pragma unroll 1
    for (int j = 0; j < NF; ++j) {
        double xi = 0.35 * pow(2.0, -(double)j/6.0);
        double sg = xi * fac;
        double u  = (f - xi) / sg;
        double v  = (u*u < 400.0) ? exp(-0.5*u*u) : 0.0;
        d_psiw[j*TN + p] = (float)(v / (double)TN);
    }
}

// ---------------- small DFTs (SIGN = -1 forward, +1 inverse) ----------------
template<int SIGN>
__device__ __forceinline__ void dft4(float2&z0,float2&z1,float2&z2,float2&z3){
    float2 t0=cadd(z0,z2), t1=csub(z0,z2), t2=cadd(z1,z3), t3=csub(z1,z3);
    const float s = (float)SIGN;
    z0 = cadd(t0,t2);
    z2 = csub(t0,t2);
    z1 = make_float2(t1.x - s*t3.y, t1.y + s*t3.x);
    z3 = make_float2(t1.x + s*t3.y, t1.y - s*t3.x);
}

template<int SIGN>
__device__ __forceinline__ void dft5(float2&z0,float2&z1,float2&z2,float2&z3,float2&z4){
    const float K1 =  0.309016994374947424f;
    const float K2 = -0.809016994374947424f;
    const float S1 =  0.951056516295153572f;
    const float S2 =  0.587785252292473129f;
    float2 t1=cadd(z1,z4), t2=cadd(z2,z3), t3=csub(z1,z4), t4=csub(z2,z3);
    float2 a = z0;
    float2 sum = cadd(a, cadd(t1,t2));
    float2 r1 = make_float2(a.x + K1*t1.x + K2*t2.x, a.y + K1*t1.y + K2*t2.y);
    float2 r2 = make_float2(a.x + K2*t1.x + K1*t2.x, a.y + K2*t1.y + K1*t2.y);
    float2 q1 = make_float2(S1*t3.x + S2*t4.x, S1*t3.y + S2*t4.y);
    float2 q2 = make_float2(S2*t3.x - S1*t4.x, S2*t3.y - S1*t4.y);
    const float s = (float)SIGN;
    z0 = sum;
    z1 = make_float2(r1.x - s*q1.y, r1.y + s*q1.x);
    z4 = make_float2(r1.x + s*q1.y, r1.y - s*q1.x);
    z2 = make_float2(r2.x - s*q2.y, r2.y + s*q2.x);
    z3 = make_float2(r2.x + s*q2.y, r2.y - s*q2.x);
}

// twiddle W_16000^{-x}, x in [0,16000): x = 125a + b
__device__ __forceinline__ float2 twb(int x, const float2* rtA, const float2* rtB){
    int a = x / 125;
    return cmul(rtA[a], rtB[x - a*125]);
}

// ---------------- radix-8 butterfly core (wp, w2 pre-conjugated for SIGN>0) ----------------
template<int SIGN>
__device__ __forceinline__ void bfly8(float2 z[8], float2 wp, float2 w2){
    const float H = 0.70710678118654752f;
    float2 w4 = cmul(w2,w2), w6 = cmul(w4,w2);
    if (SIGN < 0) {
        #pragma unroll
        for (int i=0;i<4;i++){
            float2 a=z[i], b=z[i+4];
            z[i]=cadd(a,b);
            float2 t = cmul(csub(a,b), wp);
            if (i==1) t = cmul(t, make_float2( H,-H));
            else if (i==2) t = make_float2(t.y, -t.x);
            else if (i==3) t = cmul(t, make_float2(-H,-H));
            z[i+4]=t;
        }
        dft4<-1>(z[0],z[1],z[2],z[3]);
        dft4<-1>(z[4],z[5],z[6],z[7]);
        z[1]=cmul(z[1],w2); z[2]=cmul(z[2],w4); z[3]=cmul(z[3],w6);
        z[5]=cmul(z[5],w2); z[6]=cmul(z[6],w4); z[7]=cmul(z[7],w6);
    } else {
        z[1]=cmul(z[1],w2); z[2]=cmul(z[2],w4); z[3]=cmul(z[3],w6);
        z[5]=cmul(z[5],w2); z[6]=cmul(z[6],w4); z[7]=cmul(z[7],w6);
        dft4<1>(z[0],z[1],z[2],z[3]);
        dft4<1>(z[4],z[5],z[6],z[7]);
        #pragma unroll
        for (int i=0;i<4;i++){
            float2 t = cmul(z[i+4], wp);
            if (i==1) t = cmul(t, make_float2( H, H));
            else if (i==2) t = make_float2(-t.y, t.x);
            else if (i==3) t = cmul(t, make_float2(-H, H));
            float2 a=z[i];
            z[i]=cadd(a,t); z[i+4]=csub(a,t);
        }
    }
}

// forward radix-8 first stage: reads real xs from smem, writes buf
__device__ void stage8_fwd_real(float2* buf, const float* xs, const float2* rtA, const float2* rtB){
    for (int p = threadIdx.x; p < 2000; p += NT) {
        float2 z[8];
        #pragma unroll
        for (int i=0;i<8;i++) z[i] = make_float2(xs[p + 2000*i], 0.f);
        float2 wp = twb(p, rtA, rtB);
        float2 w2 = twb(2*p, rtA, rtB);
        bfly8<-1>(z, wp, w2);
        #pragma unroll
        for (int i=0;i<8;i++) buf[p + 2000*i] = z[i];
    }
    __syncthreads();
}

// inverse radix-8 last stage: reads buf, writes U = |z| (natural time order)
__device__ void stage8_inv_abs(const float2* buf, float* U, const float2* rtA, const float2* rtB){
    for (int p = threadIdx.x; p < 2000; p += NT) {
        float2 z[8];
        #pragma unroll
        for (int i=0;i<8;i++) z[i] = buf[p + 2000*i];
        float2 wp = twb(p, rtA, rtB);   wp.y = -wp.y;
        float2 w2 = twb(2*p, rtA, rtB); w2.y = -w2.y;
        bfly8<1>(z, wp, w2);
        #pragma unroll
        for (int i=0;i<8;i++) U[p + 2000*i] = sqrtf(z[i].x*z[i].x + z[i].y*z[i].y);
    }
    __syncthreads();
}

// ---------------- fused radix-16 (= 4x4), blocks of 2000, M=125 ----------------
template<int SIGN>
__device__ void stage16f(float2* buf, const float2* rtA, const float2* rtB){
    const float CA = 0.92387953251128674f, SA = 0.38268343236508977f;
    const float H  = 0.70710678118654752f;
    for (int idx = threadIdx.x; idx < 1000; idx += NT) {
        int blk = idx / 125;
        int p   = idx - blk*125;
        int o   = blk*2000 + p;
        float2 z[16];
        #pragma unroll
        for (int i=0;i<16;i++) z[i] = buf[o + 125*i];
        float2 w1 = twb(8*p,  rtA, rtB); if (SIGN>0) w1.y=-w1.y;
        float2 w2 = twb(32*p, rtA, rtB); if (SIGN>0) w2.y=-w2.y;
        float2 w2b = cmul(w2,w2), w2c = cmul(w2b,w2);
        const float sgn = (SIGN<0)? 1.f : -1.f;
        float2 c16[4];
        c16[0] = make_float2(1.f, 0.f);
        c16[1] = make_float2(CA, -sgn*SA);
        c16[2] = make_float2( H, -sgn*H);
        c16[3] = make_float2(SA, -sgn*CA);
        if (SIGN < 0) {
            #pragma unroll
            for (int u=0;u<4;u++){
                dft4<-1>(z[u], z[u+4], z[u+8], z[u+12]);
                float2 t  = cmul(w1, c16[u]);
                float2 t2 = cmul(t,t);
                z[u+4]  = cmul(z[u+4],  t);
                z[u+8]  = cmul(z[u+8],  t2);
                z[u+12] = cmul(z[u+12], cmul(t2,t));
            }
            #pragma unroll
            for (int s=0;s<4;s++){
                dft4<-1>(z[4*s], z[4*s+1], z[4*s+2], z[4*s+3]);
                z[4*s+1]=cmul(z[4*s+1],w2); z[4*s+2]=cmul(z[4*s+2],w2b); z[4*s+3]=cmul(z[4*s+3],w2c);
            }
        } else {
            #pragma unroll
            for (int s=0;s<4;s++){
                z[4*s+1]=cmul(z[4*s+1],w2); z[4*s+2]=cmul(z[4*s+2],w2b); z[4*s+3]=cmul(z[4*s+3],w2c);
                dft4<1>(z[4*s], z[4*s+1], z[4*s+2], z[4*s+3]);
            }
            #pragma unroll
            for (int u=0;u<4;u++){
                float2 t  = cmul(w1, c16[u]);
                float2 t2 = cmul(t,t);
                z[u+4]  = cmul(z[u+4],  t);
                z[u+8]  = cmul(z[u+8],  t2);
                z[u+12] = cmul(z[u+12], cmul(t2,t));
                dft4<1>(z[u], z[u+4], z[u+8], z[u+12]);
            }
        }
        #pragma unroll
        for (int i=0;i<16;i++) buf[o + 125*i] = z[i];
    }
    __syncthreads();
}

// ---------------- radix-5 middle stage (M in {5,25}) ----------------
template<int M, int C, int SIGN>
__device__ void stage5n(float2* buf, const float2* rtA, const float2* rtB){
    for (int idx = threadIdx.x; idx < 3200; idx += NT) {
        int blk = idx / M;
        int p   = idx - blk*M;
        int o   = blk*(5*M) + p;
        float2 z0=buf[o], z1=buf[o+M], z2=buf[o+2*M], z3=buf[o+3*M], z4=buf[o+4*M];
        float2 w = twb(C*p, rtA, rtB); if (SIGN>0) w.y=-w.y;
        float2 ww = cmul(w,w);
        float2 w3 = cmul(ww,w);
        float2 w4 = cmul(ww,ww);
        if (SIGN > 0) {
            z1=cmul(z1,w); z2=cmul(z2,ww); z3=cmul(z3,w3); z4=cmul(z4,w4);
            dft5<1>(z0,z1,z2,z3,z4);
        } else {
            dft5<-1>(z0,z1,z2,z3,z4);
            z1=cmul(z1,w); z2=cmul(z2,ww); z3=cmul(z3,w3); z4=cmul(z4,w4);
        }
        buf[o]=z0; buf[o+M]=z1; buf[o+2*M]=z2; buf[o+3*M]=z3; buf[o+4*M]=z4;
    }
    __syncthreads();
}

// forward radix-5 last stage (M=1, no twiddle): reads buf, writes global X
__device__ void stage5_fwd_store(const float2* buf, float2* Xo){
    for (int b5 = threadIdx.x; b5 < 3200; b5 += NT) {
        int o = 5*b5;
        float2 z0=buf[o], z1=buf[o+1], z2=buf[o+2], z3=buf[o+3], z4=buf[o+4];
        dft5<-1>(z0,z1,z2,z3,z4);
        Xo[o]=z0; Xo[o+1]=z1; Xo[o+2]=z2; Xo[o+3]=z3; Xo[o+4]=z4;
    }
}

// inverse radix-5 first stage (M=1, no twiddle): reads global X * psi, writes buf
__device__ void stage5_inv_load(float2* buf, const float2* __restrict__ Xb, const float* __restrict__ pw){
    for (int b5 = threadIdx.x; b5 < 3200; b5 += NT) {
        int o = 5*b5;
        float2 z0,z1,z2,z3,z4;
        { float2 v=Xb[o  ]; float w=pw[o  ]; z0=make_float2(v.x*w, v.y*w); }
        { float2 v=Xb[o+1]; float w=pw[o+1]; z1=make_float2(v.x*w, v.y*w); }
        { float2 v=Xb[o+2]; float w=pw[o+2]; z2=make_float2(v.x*w, v.y*w); }
        { float2 v=Xb[o+3]; float w=pw[o+3]; z3=make_float2(v.x*w, v.y*w); }
        { float2 v=Xb[o+4]; float w=pw[o+4]; z4=make_float2(v.x*w, v.y*w); }
        dft5<1>(z0,z1,z2,z3,z4);
        buf[o]=z0; buf[o+1]=z1; buf[o+2]=z2; buf[o+3]=z3; buf[o+4]=z4;
    }
    __syncthreads();
}

__device__ void init_tables(float2* rtA, float2* rtB, float* sphi){
    for (int i = threadIdx.x; i < 128; i += NT) rtA[i] = d_rtA[i];
    for (int i = threadIdx.x; i < 125; i += NT) rtB[i] = d_rtB[i];
    for (int i = threadIdx.x; i < NTAPS; i += NT) sphi[i] = d_phiw[i];
}

// warp-per-output smoothing: conflict-free coalesced LDS, shuffle reduce
__device__ void smooth(const float* __restrict__ S, const float* __restrict__ sphi, float* dst){
    int w = threadIdx.x >> 5, l = threadIdx.x & 31;
    for (int m0 = w; m0 < NOUT; m0 += NT/32) {
        int center = 64*m0 + DH;
        float acc = 0.f;
        #pragma unroll
        for (int i = 0; i < (NTAPS-1)/32; ++i) {
            int id = center - l - 32*i;
            if (id >= TN) id -= TN;
            if (id < 0)   id += TN;
            acc += sphi[l + 32*i] * S[id];
        }
        if (l == 0) {
            int id = center - (NTAPS-1);
            if (id < 0) id += TN;
            acc += sphi[NTAPS-1] * S[id];
        }
        #pragma unroll
        for (int o = 16; o; o >>= 1) acc += __shfl_down_sync(0xffffffffu, acc, o);
        if (l == 0) dst[m0] = acc;
    }
}

// ---------------- kernel 1: forward FFT of x (+ S0) ----------------
__global__ __launch_bounds__(NT, 1) void k_fwd(const float* __restrict__ x){
    extern __shared__ __align__(16) unsigned char sm[];
    float2* buf = (float2*)sm;                       // 16000 complex
    float*  xs  = (float*)(sm + TN*sizeof(float2));  // 16000 real
    __shared__ float2 rtA[128]; __shared__ float2 rtB[125]; __shared__ float sphi[NTAPS];
    int b = blockIdx.x;
    init_tables(rtA, rtB, sphi);
    const float* xb = x + b*TN;
    for (int n = threadIdx.x; n < TN; n += NT) xs[n] = xb[n];
    __syncthreads();
    smooth(xs, sphi, &d_S1[(b*NCH + 0)*NOUT]);       // S0 in time domain
    stage8_fwd_real(buf, xs, rtA, rtB);
    stage16f<-1>(buf, rtA, rtB);
    stage5n<25,128,-1>(buf, rtA, rtB);
    stage5n<5,640,-1>(buf, rtA, rtB);
    stage5_fwd_store(buf, d_X + b*TN);
}

// ---------------- kernel 2: band-pass ifft + |.| + smoothing ----------------
__global__ __launch_bounds__(NT, 1) void k_band(){
    extern __shared__ __align__(16) unsigned char sm[];
    float2* buf = (float2*)sm;
    float*  U   = (float*)(sm + TN*sizeof(float2));
    __shared__ float2 rtA[128]; __shared__ float2 rtB[125]; __shared__ float sphi[NTAPS];
    int j = blockIdx.x, b = blockIdx.y;
    init_tables(rtA, rtB, sphi);
    __syncthreads();
    stage5_inv_load(buf, d_X + b*TN, d_psiw + j*TN);
    stage5n<5,640,1>(buf, rtA, rtB);
    stage5n<25,128,1>(buf, rtA, rtB);
    stage16f<1>(buf, rtA, rtB);
    stage8_inv_abs(buf, U, rtA, rtB);
    smooth(U, sphi, &d_S1[(b*NCH + 1 + j)*NOUT]);
}

// ---------------- kernel 3: channel-group means ----------------
__global__ void k_reduce(float* __restrict__ out){
    int i = blockIdx.x * blockDim.x + threadIdx.x;
    if (i >= NB*3*NOUT) return;
    int m0 = i % NOUT;
    int g  = (i / NOUT) % 3;
    int b  = i / (3*NOUT);
    int c0 = (g==0) ? 0 : (g==1 ? 12 : 24);
    int nc = (g==2) ? 13 : 12;
    float acc = 0.f;
    for (int c = 0; c < nc; ++c) acc += d_S1[(b*NCH + c0 + c)*NOUT + m0];
    out[i] = acc / (float)nc;
}

// ---------------- launch ----------------
extern "C" void kernel_launch(void* const* d_in, const int* in_sizes, int n_in,
                              void* d_out, int out_size) {
    (void)in_sizes; (void)n_in; (void)out_size;
    const float* x = (const float*)d_in[0];
    float* out = (float*)d_out;
    const int smbytes = TN*(int)sizeof(float2) + TN*(int)sizeof(float);  // 192000
    cudaFuncSetAttribute(k_fwd,  cudaFuncAttributeMaxDynamicSharedMemorySize, smbytes);
    cudaFuncSetAttribute(k_band, cudaFuncAttributeMaxDynamicSharedMemorySize, smbytes);
    prep_phi<<<NTAPS, 32>>>();
    prep_tw<<<1, 128>>>();
    prep_psi<<<(TN + 255)/256, 256>>>();
    k_fwd<<<NB, NT, smbytes>>>(x);
    k_band<<<dim3(NF, NB), NT, smbytes>>>();
    k_reduce<<<(NB*3*NOUT + 255)/256, 256>>>(out);
}

// round 5
// speedup vs baseline: 1.6725x; 1.0799x over previous
#include <cuda_runtime.h>
#include <math.h>

#define TN 16000
#define NT 1024
#define NF 36
#define NB 64
#define NOUT 250
#define DH 128
#define NTAPS 257
#define KPHI 569
#define NCH 37

// ---------------- static device scratch ----------------
__device__ float2 d_X[NB * TN];        // scrambled forward FFT of x (8 MB, L2-resident)
__device__ float  d_psiw[NF * TN];     // psi_hat (scrambled order) / TN
__device__ float  d_phiw[NTAPS];       // time-domain lowpass taps
__device__ float2 d_rtA[128];          // W_16000^{-125 i}
__device__ float2 d_rtB[125];          // W_16000^{-i}
__device__ float  d_S1[NB * NCH * NOUT];

// ---------------- complex helpers ----------------
__device__ __forceinline__ float2 cmul(float2 a, float2 b) {
    return make_float2(a.x*b.x - a.y*b.y, a.x*b.y + a.y*b.x);
}
__device__ __forceinline__ float2 cadd(float2 a, float2 b){ return make_float2(a.x+b.x, a.y+b.y); }
__device__ __forceinline__ float2 csub(float2 a, float2 b){ return make_float2(a.x-b.x, a.y-b.y); }

// ---------------- prep kernels ----------------
__global__ void prep_phi() {
    int tap  = blockIdx.x;
    int lane = threadIdx.x;
    int d = tap - DH;
    const double sp = 0.35 / 64.0;
    const double PI2 = 6.283185307179586476925286766559;
    double acc = 0.0;
    for (int k = 1 + lane; k <= KPHI; k += 32) {
        double f = (double)k / (double)TN;
        double g = exp(-f*f / (2.0*sp*sp));
        acc += g * cos(PI2 * (double)k * (double)d / (double)TN);
    }
    for (int o = 16; o; o >>= 1) acc += __shfl_down_sync(0xffffffffu, acc, o);
    if (lane == 0) d_phiw[tap] = (float)((1.0 + 2.0*acc) / (double)TN);
}

__global__ void prep_tw() {
    int i = threadIdx.x;
    if (i < 128) { double s, c; sincospi(-(double)i/64.0,   &s, &c); d_rtA[i] = make_float2((float)c, (float)s); }
    if (i < 125) { double s, c; sincospi(-(double)i/8000.0, &s, &c); d_rtB[i] = make_float2((float)c, (float)s); }
}

__global__ void prep_psi() {
    int p = blockIdx.x * blockDim.x + threadIdx.x;
    if (p >= TN) return;
    // digit reversal for DIF radices [4,4,10,10,10] (position p -> frequency k)
    int k = (p/4000) + 4*((p/1000)%4) + 16*((p/100)%10) + 160*((p/10)%10) + 1600*(p%10);
    double f = (k < TN/2) ? (double)k / (double)TN : (double)(k - TN) / (double)TN;
    const double r   = pow(2.0, 1.0/6.0);
    const double fac = (r - 1.0) / (r + 1.0);
    #pragma unroll 1
    for (int j = 0; j < NF; ++j) {
        double xi = 0.35 * pow(2.0, -(double)j/6.0);
        double sg = xi * fac;
        double u  = (f - xi) / sg;
        double v  = (u*u < 400.0) ? exp(-0.5*u*u) : 0.0;
        d_psiw[j*TN + p] = (float)(v / (double)TN);
    }
}

// ---------------- small DFTs (SIGN = -1 forward, +1 inverse) ----------------
template<int SIGN>
__device__ __forceinline__ void dft4(float2&z0,float2&z1,float2&z2,float2&z3){
    float2 t0=cadd(z0,z2), t1=csub(z0,z2), t2=cadd(z1,z3), t3=csub(z1,z3);
    const float s = (float)SIGN;
    z0 = cadd(t0,t2);
    z2 = csub(t0,t2);
    z1 = make_float2(t1.x - s*t3.y, t1.y + s*t3.x);
    z3 = make_float2(t1.x + s*t3.y, t1.y - s*t3.x);
}

template<int SIGN>
__device__ __forceinline__ void dft5(float2&z0,float2&z1,float2&z2,float2&z3,float2&z4){
    const float K1 =  0.309016994374947424f;
    const float K2 = -0.809016994374947424f;
    const float S1 =  0.951056516295153572f;
    const float S2 =  0.587785252292473129f;
    float2 t1=cadd(z1,z4), t2=cadd(z2,z3), t3=csub(z1,z4), t4=csub(z2,z3);
    float2 a = z0;
    float2 sum = cadd(a, cadd(t1,t2));
    float2 r1 = make_float2(a.x + K1*t1.x + K2*t2.x, a.y + K1*t1.y + K2*t2.y);
    float2 r2 = make_float2(a.x + K2*t1.x + K1*t2.x, a.y + K2*t1.y + K1*t2.y);
    float2 q1 = make_float2(S1*t3.x + S2*t4.x, S1*t3.y + S2*t4.y);
    float2 q2 = make_float2(S2*t3.x - S1*t4.x, S2*t3.y - S1*t4.y);
    const float s = (float)SIGN;
    z0 = sum;
    z1 = make_float2(r1.x - s*q1.y, r1.y + s*q1.x);
    z4 = make_float2(r1.x + s*q1.y, r1.y - s*q1.x);
    z2 = make_float2(r2.x - s*q2.y, r2.y + s*q2.x);
    z3 = make_float2(r2.x + s*q2.y, r2.y - s*q2.x);
}

// twiddle W_16000^{-x}, x in [0,16000): x = 125a + b
__device__ __forceinline__ float2 twb(int x, const float2* rtA, const float2* rtB){
    int a = x / 125;
    return cmul(rtA[a], rtB[x - a*125]);
}

// ---------------- fused radix-16 (= radix-4 M=4000, radix-4 M=1000), subN=16000 ----------------
// forward first stage: reads real xs, writes buf
__device__ void stage16_fwd(float2* buf, const float* xs, const float2* rtA, const float2* rtB){
    const float2 c16_1 = make_float2(0.92387953251128674f, -0.38268343236508977f);
    const float2 c16_2 = make_float2(0.70710678118654752f, -0.70710678118654752f);
    const float2 c16_3 = make_float2(0.38268343236508977f, -0.92387953251128674f);
    for (int p = threadIdx.x; p < 1000; p += NT) {
        float2 z[16];
        #pragma unroll
        for (int j=0;j<4;j++)
            #pragma unroll
            for (int i=0;i<4;i++)
                z[4*j+i] = make_float2(xs[p + 1000*j + 4000*i], 0.f);
        float2 a = twb(p, rtA, rtB);
        float2 b = twb(4*p, rtA, rtB);
        #pragma unroll
        for (int j=0;j<4;j++) dft4<-1>(z[4*j+0], z[4*j+1], z[4*j+2], z[4*j+3]);   // over i -> s1
        #pragma unroll
        for (int j=0;j<4;j++){
            float2 t = (j==0)? a : (j==1? cmul(a,c16_1) : (j==2? cmul(a,c16_2) : cmul(a,c16_3)));
            float2 t2 = cmul(t,t);
            z[4*j+1]=cmul(z[4*j+1],t); z[4*j+2]=cmul(z[4*j+2],t2); z[4*j+3]=cmul(z[4*j+3],cmul(t2,t));
        }
        #pragma unroll
        for (int s1=0;s1<4;s1++) dft4<-1>(z[s1], z[4+s1], z[8+s1], z[12+s1]);     // over j -> s2
        float2 b2 = cmul(b,b), b3 = cmul(b2,b);
        #pragma unroll
        for (int s1=0;s1<4;s1++){ z[4+s1]=cmul(z[4+s1],b); z[8+s1]=cmul(z[8+s1],b2); z[12+s1]=cmul(z[12+s1],b3); }
        #pragma unroll
        for (int s1=0;s1<4;s1++)
            #pragma unroll
            for (int s2=0;s2<4;s2++)
                buf[s1*4000 + s2*1000 + p] = z[4*s2+s1];
    }
    __syncthreads();
}

// inverse last stage: reads buf, writes U = |z| (natural time order)
__device__ void stage16_inv_abs(const float2* buf, float* U, const float2* rtA, const float2* rtB){
    const float2 c16_1 = make_float2(0.92387953251128674f,  0.38268343236508977f);
    const float2 c16_2 = make_float2(0.70710678118654752f,  0.70710678118654752f);
    const float2 c16_3 = make_float2(0.38268343236508977f,  0.92387953251128674f);
    for (int p = threadIdx.x; p < 1000; p += NT) {
        float2 z[16];
        #pragma unroll
        for (int s1=0;s1<4;s1++)
            #pragma unroll
            for (int s2=0;s2<4;s2++)
                z[4*s2+s1] = buf[s1*4000 + s2*1000 + p];
        float2 a = twb(p, rtA, rtB);   a.y = -a.y;
        float2 b = twb(4*p, rtA, rtB); b.y = -b.y;
        float2 b2 = cmul(b,b), b3 = cmul(b2,b);
        #pragma unroll
        for (int s1=0;s1<4;s1++){ z[4+s1]=cmul(z[4+s1],b); z[8+s1]=cmul(z[8+s1],b2); z[12+s1]=cmul(z[12+s1],b3); }
        #pragma unroll
        for (int s1=0;s1<4;s1++) dft4<1>(z[s1], z[4+s1], z[8+s1], z[12+s1]);      // over s2 -> j
        #pragma unroll
        for (int j=0;j<4;j++){
            float2 t = (j==0)? a : (j==1? cmul(a,c16_1) : (j==2? cmul(a,c16_2) : cmul(a,c16_3)));
            float2 t2 = cmul(t,t);
            z[4*j+1]=cmul(z[4*j+1],t); z[4*j+2]=cmul(z[4*j+2],t2); z[4*j+3]=cmul(z[4*j+3],cmul(t2,t));
        }
        #pragma unroll
        for (int j=0;j<4;j++) dft4<1>(z[4*j+0], z[4*j+1], z[4*j+2], z[4*j+3]);    // over s1 -> i
        #pragma unroll
        for (int j=0;j<4;j++)
            #pragma unroll
            for (int i=0;i<4;i++){
                float2 v = z[4*j+i];
                U[p + 1000*j + 4000*i] = sqrtf(v.x*v.x + v.y*v.y);
            }
    }
    __syncthreads();
}

// ---------------- fused radix-10 (= 2x5) middle stages; CC = 16000/subN ----------------
template<int M, int CC, int SIGN>
__device__ void stage10(float2* buf, const float2* rtA, const float2* rtB){
    const float c1x=0.809016994374947424f, c1y=0.587785252292473129f;
    const float c2x=0.309016994374947424f, c2y=0.951056516295153572f;
    const float sg = (SIGN<0)? 1.f : -1.f;
    const float2 w10_1 = make_float2( c1x, -sg*c1y);
    const float2 w10_2 = make_float2( c2x, -sg*c2y);
    const float2 w10_3 = make_float2(-c2x, -sg*c2y);
    const float2 w10_4 = make_float2(-c1x, -sg*c1y);
    for (int idx = threadIdx.x; idx < 1600; idx += NT) {
        int blk = idx / M;
        int p   = idx - blk*M;
        int o   = blk*(10*M) + p;
        float2 z[10];
        #pragma unroll
        for (int i=0;i<10;i++) z[i] = buf[o + M*i];
        float2 v = twb(CC*p, rtA, rtB);
        if (SIGN > 0) v.y = -v.y;
        float2 b  = cmul(v,v);
        float2 b2 = cmul(b,b);
        float2 b3 = cmul(b2,b);
        float2 b4 = cmul(b2,b2);
        float2 m1 = cmul(w10_1, v);
        float2 m2 = cmul(w10_2, v);
        float2 m3 = cmul(w10_3, v);
        float2 m4 = cmul(w10_4, v);
        if (SIGN < 0) {
            float2 e0=cadd(z[0],z[5]), e1=cadd(z[1],z[6]), e2=cadd(z[2],z[7]), e3=cadd(z[3],z[8]), e4=cadd(z[4],z[9]);
            float2 q0=cmul(csub(z[0],z[5]), v ), q1=cmul(csub(z[1],z[6]), m1),
                   q2=cmul(csub(z[2],z[7]), m2), q3=cmul(csub(z[3],z[8]), m3),
                   q4=cmul(csub(z[4],z[9]), m4);
            dft5<-1>(e0,e1,e2,e3,e4);
            dft5<-1>(q0,q1,q2,q3,q4);
            z[0]=e0;          z[1]=q0;
            z[2]=cmul(e1,b);  z[3]=cmul(q1,b);
            z[4]=cmul(e2,b2); z[5]=cmul(q2,b2);
            z[6]=cmul(e3,b3); z[7]=cmul(q3,b3);
            z[8]=cmul(e4,b4); z[9]=cmul(q4,b4);
        } else {
            float2 E0=z[0], E1=cmul(z[2],b), E2=cmul(z[4],b2), E3=cmul(z[6],b3), E4=cmul(z[8],b4);
            float2 O0=z[1], O1=cmul(z[3],b), O2=cmul(z[5],b2), O3=cmul(z[7],b3), O4=cmul(z[9],b4);
            dft5<1>(E0,E1,E2,E3,E4);
            dft5<1>(O0,O1,O2,O3,O4);
            O0=cmul(O0,v ); O1=cmul(O1,m1); O2=cmul(O2,m2); O3=cmul(O3,m3); O4=cmul(O4,m4);
            z[0]=cadd(E0,O0); z[5]=csub(E0,O0);
            z[1]=cadd(E1,O1); z[6]=csub(E1,O1);
            z[2]=cadd(E2,O2); z[7]=csub(E2,O2);
            z[3]=cadd(E3,O3); z[8]=csub(E3,O3);
            z[4]=cadd(E4,O4); z[9]=csub(E4,O4);
        }
        #pragma unroll
        for (int i=0;i<10;i++) buf[o + M*i] = z[i];
    }
    __syncthreads();
}

// forward last stage: radix-10 M=1, no twiddle, store natural to global X (vectorized)
__device__ void stage10_fwd_store(const float2* buf, float2* __restrict__ Xo){
    const float c1x=0.809016994374947424f, c1y=0.587785252292473129f;
    const float c2x=0.309016994374947424f, c2y=0.951056516295153572f;
    const float2 w1 = make_float2( c1x, -c1y);
    const float2 w2 = make_float2( c2x, -c2y);
    const float2 w3 = make_float2(-c2x, -c2y);
    const float2 w4 = make_float2(-c1x, -c1y);
    for (int blk = threadIdx.x; blk < 1600; blk += NT) {
        int o = 10*blk;
        float2 z[10];
        #pragma unroll
        for (int i=0;i<10;i++) z[i] = buf[o+i];
        float2 e0=cadd(z[0],z[5]), e1=cadd(z[1],z[6]), e2=cadd(z[2],z[7]), e3=cadd(z[3],z[8]), e4=cadd(z[4],z[9]);
        float2 q0=csub(z[0],z[5]),           q1=cmul(csub(z[1],z[6]), w1),
               q2=cmul(csub(z[2],z[7]), w2), q3=cmul(csub(z[3],z[8]), w3),
               q4=cmul(csub(z[4],z[9]), w4);
        dft5<-1>(e0,e1,e2,e3,e4);
        dft5<-1>(q0,q1,q2,q3,q4);
        float4* X4 = (float4*)(Xo + o);
        X4[0] = make_float4(e0.x,e0.y,q0.x,q0.y);
        X4[1] = make_float4(e1.x,e1.y,q1.x,q1.y);
        X4[2] = make_float4(e2.x,e2.y,q2.x,q2.y);
        X4[3] = make_float4(e3.x,e3.y,q3.x,q3.y);
        X4[4] = make_float4(e4.x,e4.y,q4.x,q4.y);
    }
}

// inverse first stage: radix-10 M=1, no twiddle, reads global X * psi (vectorized)
__device__ void stage10_inv_load(float2* buf, const float2* __restrict__ Xb, const float* __restrict__ pw){
    const float c1x=0.809016994374947424f, c1y=0.587785252292473129f;
    const float c2x=0.309016994374947424f, c2y=0.951056516295153572f;
    const float2 w1 = make_float2( c1x,  c1y);
    const float2 w2 = make_float2( c2x,  c2y);
    const float2 w3 = make_float2(-c2x,  c2y);
    const float2 w4 = make_float2(-c1x,  c1y);
    for (int blk = threadIdx.x; blk < 1600; blk += NT) {
        int o = 10*blk;
        const float4* X4 = (const float4*)(Xb + o);
        const float2* P2 = (const float2*)(pw + o);
        float2 z[10];
        #pragma unroll
        for (int i=0;i<5;i++){
            float4 xv = X4[i];
            float2 wv = P2[i];
            z[2*i]   = make_float2(xv.x*wv.x, xv.y*wv.x);
            z[2*i+1] = make_float2(xv.z*wv.y, xv.w*wv.y);
        }
        float2 E0=z[0], E1=z[2], E2=z[4], E3=z[6], E4=z[8];
        float2 O0=z[1], O1=z[3], O2=z[5], O3=z[7], O4=z[9];
        dft5<1>(E0,E1,E2,E3,E4);
        dft5<1>(O0,O1,O2,O3,O4);
        O1=cmul(O1,w1); O2=cmul(O2,w2); O3=cmul(O3,w3); O4=cmul(O4,w4);
        buf[o  ]=cadd(E0,O0); buf[o+5]=csub(E0,O0);
        buf[o+1]=cadd(E1,O1); buf[o+6]=csub(E1,O1);
        buf[o+2]=cadd(E2,O2); buf[o+7]=csub(E2,O2);
        buf[o+3]=cadd(E3,O3); buf[o+8]=csub(E3,O3);
        buf[o+4]=cadd(E4,O4); buf[o+9]=csub(E4,O4);
    }
    __syncthreads();
}

__device__ void init_tables(float2* rtA, float2* rtB, float* sphi){
    for (int i = threadIdx.x; i < 128; i += NT) rtA[i] = d_rtA[i];
    for (int i = threadIdx.x; i < 125; i += NT) rtB[i] = d_rtB[i];
    for (int i = threadIdx.x; i < NTAPS; i += NT) sphi[i] = d_phiw[i];
}

// warp-per-output smoothing: conflict-free coalesced LDS, shuffle reduce
__device__ void smooth(const float* __restrict__ S, const float* __restrict__ sphi, float* dst){
    int w = threadIdx.x >> 5, l = threadIdx.x & 31;
    for (int m0 = w; m0 < NOUT; m0 += NT/32) {
        int center = 64*m0 + DH;
        float acc = 0.f;
        #pragma unroll
        for (int i = 0; i < (NTAPS-1)/32; ++i) {
            int id = center - l - 32*i;
            if (id >= TN) id -= TN;
            if (id < 0)   id += TN;
            acc += sphi[l + 32*i] * S[id];
        }
        if (l == 0) {
            int id = center - (NTAPS-1);
            if (id < 0) id += TN;
            acc += sphi[NTAPS-1] * S[id];
        }
        #pragma unroll
        for (int o = 16; o; o >>= 1) acc += __shfl_down_sync(0xffffffffu, acc, o);
        if (l == 0) dst[m0] = acc;
    }
}

// ---------------- kernel 1: forward FFT of x (+ S0) ----------------
__global__ __launch_bounds__(NT, 1) void k_fwd(const float* __restrict__ x){
    extern __shared__ __align__(16) unsigned char sm[];
    float2* buf = (float2*)sm;                       // 16000 complex
    float*  xs  = (float*)(sm + TN*sizeof(float2));  // 16000 real
    __shared__ float2 rtA[128]; __shared__ float2 rtB[125]; __shared__ float sphi[NTAPS];
    int b = blockIdx.x;
    init_tables(rtA, rtB, sphi);
    const float4* xb4 = (const float4*)(x + b*TN);
    float4* xs4 = (float4*)xs;
    for (int n = threadIdx.x; n < TN/4; n += NT) xs4[n] = xb4[n];
    __syncthreads();
    smooth(xs, sphi, &d_S1[(b*NCH + 0)*NOUT]);       // S0 in time domain
    stage16_fwd(buf, xs, rtA, rtB);
    stage10<100,16,-1>(buf, rtA, rtB);
    stage10<10,160,-1>(buf, rtA, rtB);
    stage10_fwd_store(buf, d_X + b*TN);
}

// ---------------- kernel 2: band-pass ifft + |.| + smoothing ----------------
__global__ __launch_bounds__(NT, 1) void k_band(){
    extern __shared__ __align__(16) unsigned char sm[];
    float2* buf = (float2*)sm;
    float*  U   = (float*)(sm + TN*sizeof(float2));
    __shared__ float2 rtA[128]; __shared__ float2 rtB[125]; __shared__ float sphi[NTAPS];
    int j = blockIdx.x, b = blockIdx.y;
    init_tables(rtA, rtB, sphi);
    __syncthreads();
    stage10_inv_load(buf, d_X + b*TN, d_psiw + j*TN);
    stage10<10,160,1>(buf, rtA, rtB);
    stage10<100,16,1>(buf, rtA, rtB);
    stage16_inv_abs(buf, U, rtA, rtB);
    smooth(U, sphi, &d_S1[(b*NCH + 1 + j)*NOUT]);
}

// ---------------- kernel 3: channel-group means ----------------
__global__ void k_reduce(float* __restrict__ out){
    int i = blockIdx.x * blockDim.x + threadIdx.x;
    if (i >= NB*3*NOUT) return;
    int m0 = i % NOUT;
    int g  = (i / NOUT) % 3;
    int b  = i / (3*NOUT);
    int c0 = (g==0) ? 0 : (g==1 ? 12 : 24);
    int nc = (g==2) ? 13 : 12;
    float acc = 0.f;
    for (int c = 0; c < nc; ++c) acc += d_S1[(b*NCH + c0 + c)*NOUT + m0];
    out[i] = acc / (float)nc;
}

// ---------------- launch ----------------
extern "C" void kernel_launch(void* const* d_in, const int* in_sizes, int n_in,
                              void* d_out, int out_size) {
    (void)in_sizes; (void)n_in; (void)out_size;
    const float* x = (const float*)d_in[0];
    float* out = (float*)d_out;
    const int smbytes = TN*(int)sizeof(float2) + TN*(int)sizeof(float);  // 192000
    cudaFuncSetAttribute(k_fwd,  cudaFuncAttributeMaxDynamicSharedMemorySize, smbytes);
    cudaFuncSetAttribute(k_band, cudaFuncAttributeMaxDynamicSharedMemorySize, smbytes);
    prep_phi<<<NTAPS, 32>>>();
    prep_tw<<<1, 128>>>();
    prep_psi<<<(TN + 255)/256, 256>>>();
    k_fwd<<<NB, NT, smbytes>>>(x);
    k_band<<<dim3(NF, NB), NT, smbytes>>>();
    k_reduce<<<(NB*3*NOUT + 255)/256, 256>>>(out);
}